// round 2
// baseline (speedup 1.0000x reference)
#include <cuda_runtime.h>
#include <math.h>
#include <stdint.h>
#include <stddef.h>

// ---------------- problem constants ----------------
#define B_      32
#define CIN     3
#define HIN     32
#define C0      256
#define HO      29          // conv1 output spatial
#define NCAP    16
#define OC2     4096        // NCAP*C0
#define SO      13          // pcaps output spatial
#define NPOS    169         // 13*13
#define ROUTES  43264       // C0*NPOS
#define NCLS    10
#define OD      4
#define NGEMM   5408        // B_*NPOS
#define KGEMM   4096        // C0*16

// ---------------- scratch (static device memory; no allocations) ----------------
__device__ float g_h[B_ * C0 * HO * HO];                 // 27.6 MB  stem conv out
__device__ float g_col[(size_t)NGEMM * KGEMM];           // 88.6 MB  im2col
__device__ float g_P[(size_t)OC2 * NGEMM];               // 88.6 MB  pcaps conv out [oc][n]
__device__ float g_u[(size_t)B_ * ROUTES * NCAP];        // 88.6 MB  squashed capsules
__device__ float g_s[B_ * NCLS * OD];                    // routing accumulator
__device__ float g_vacc[B_ * NCLS * OD];                 // sum of v_t  (implicit b_log)

// ---------------- init: zero the tiny routing state ----------------
__global__ void k_zero() {
    for (int i = threadIdx.x; i < B_ * NCLS * OD; i += blockDim.x) {
        g_s[i] = 0.f;
        g_vacc[i] = 0.f;
    }
}

// ---------------- stem conv 4x4 stride 1 + relu ----------------
// grid (8 oc-groups, 32 batch), 256 threads. Whole image + 32 oc of weights in smem.
__global__ __launch_bounds__(256) void k_conv1(const float* __restrict__ x,
                                               const float* __restrict__ w,
                                               const float* __restrict__ bias) {
    __shared__ float simg[CIN * HIN * HIN];   // 3072 floats
    __shared__ float swt[32 * CIN * 16];      // 1536 floats
    __shared__ float sb[32];
    const int b = blockIdx.y, ocg = blockIdx.x;
    const int tid = threadIdx.x;

    for (int i = tid; i < CIN * HIN * HIN; i += 256)
        simg[i] = x[b * CIN * HIN * HIN + i];
    for (int i = tid; i < 32 * 48; i += 256)
        swt[i] = w[(ocg * 32) * 48 + i];
    if (tid < 32) sb[tid] = bias[ocg * 32 + tid];
    __syncthreads();

    // items: oc(32) x p(29) x qgroup(8 of 4 columns)
    for (int it = tid; it < 32 * 29 * 8; it += 256) {
        int oc = it / (29 * 8);
        int r  = it % (29 * 8);
        int p  = r >> 3;
        int qb = (r & 7) * 4;
        float a0 = sb[oc], a1 = a0, a2 = a0, a3 = a0;
        #pragma unroll
        for (int ic = 0; ic < CIN; ic++) {
            #pragma unroll
            for (int ky = 0; ky < 4; ky++) {
                const float* rp = &simg[ic * 1024 + (p + ky) * 32 + qb];
                const float* wp = &swt[oc * 48 + ic * 16 + ky * 4];
                float r0 = rp[0], r1 = rp[1], r2 = rp[2], r3 = rp[3];
                float r4 = (qb + 4 < 32) ? rp[4] : 0.f;
                float r5 = (qb + 5 < 32) ? rp[5] : 0.f;
                float r6 = (qb + 6 < 32) ? rp[6] : 0.f;
                float w0 = wp[0], w1 = wp[1], w2 = wp[2], w3 = wp[3];
                a0 += r0 * w0 + r1 * w1 + r2 * w2 + r3 * w3;
                a1 += r1 * w0 + r2 * w1 + r3 * w2 + r4 * w3;
                a2 += r2 * w0 + r3 * w1 + r4 * w2 + r5 * w3;
                a3 += r3 * w0 + r4 * w1 + r5 * w2 + r6 * w3;
            }
        }
        size_t base = (((size_t)b * C0 + ocg * 32 + oc) * HO + p) * HO;
        if (qb + 0 < HO) g_h[base + qb + 0] = fmaxf(a0, 0.f);
        if (qb + 1 < HO) g_h[base + qb + 1] = fmaxf(a1, 0.f);
        if (qb + 2 < HO) g_h[base + qb + 2] = fmaxf(a2, 0.f);
        if (qb + 3 < HO) g_h[base + qb + 3] = fmaxf(a3, 0.f);
    }
}

// ---------------- im2col for the stride-2 4x4 conv ----------------
// col[n][k], n = b*169 + y*13 + x, k = ic*16 + ky*4 + kx
__global__ void k_im2col() {
    const int n = blockIdx.x;
    const int b = n / NPOS, s = n % NPOS;
    const int y = s / SO, xq = s % SO;
    const size_t ob = (size_t)n * KGEMM;
    for (int k = threadIdx.x; k < KGEMM; k += blockDim.x) {
        int ic = k >> 4, kp = k & 15;
        int ky = kp >> 2, kx = kp & 3;
        g_col[ob + k] =
            g_h[(((size_t)b * C0 + ic) * HO + 2 * y + ky) * HO + 2 * xq + kx];
    }
}

// ---------------- SGEMM: P[m][n] = sum_k A[m][k]*col[n][k] ----------------
// A = pcaps_w flattened [4096][4096]. 128x128x16 tiles, 8x8/thread, double-buffered.
__global__ __launch_bounds__(256) void k_sgemm(const float* __restrict__ A) {
    __shared__ float As[2][16][128];
    __shared__ float Bs[2][16][128];
    const int Kd = KGEMM, Nd = NGEMM;
    const int tid = threadIdx.x;
    const int m0 = blockIdx.y * 128;
    const int n0 = blockIdx.x * 128;
    const int tx = tid & 15, ty = tid >> 4;

    const int ar0 = tid >> 2,          ac0 = (tid & 3) * 4;
    const int ar1 = (tid + 256) >> 2,  ac1 = ((tid + 256) & 3) * 4;
    const float* Ab = A + (size_t)m0 * Kd;

    float4 ra0, ra1, rb0, rb1;
    // load tile 0
    {
        ra0 = *(const float4*)&Ab[(size_t)ar0 * Kd + ac0];
        ra1 = *(const float4*)&Ab[(size_t)ar1 * Kd + ac1];
        int br0 = n0 + ar0, br1 = n0 + ar1;
        rb0 = (br0 < Nd) ? *(const float4*)&g_col[(size_t)br0 * Kd + ac0]
                         : make_float4(0.f, 0.f, 0.f, 0.f);
        rb1 = (br1 < Nd) ? *(const float4*)&g_col[(size_t)br1 * Kd + ac1]
                         : make_float4(0.f, 0.f, 0.f, 0.f);
        As[0][ac0 + 0][ar0] = ra0.x; As[0][ac0 + 1][ar0] = ra0.y;
        As[0][ac0 + 2][ar0] = ra0.z; As[0][ac0 + 3][ar0] = ra0.w;
        As[0][ac1 + 0][ar1] = ra1.x; As[0][ac1 + 1][ar1] = ra1.y;
        As[0][ac1 + 2][ar1] = ra1.z; As[0][ac1 + 3][ar1] = ra1.w;
        Bs[0][ac0 + 0][ar0] = rb0.x; Bs[0][ac0 + 1][ar0] = rb0.y;
        Bs[0][ac0 + 2][ar0] = rb0.z; Bs[0][ac0 + 3][ar0] = rb0.w;
        Bs[0][ac1 + 0][ar1] = rb1.x; Bs[0][ac1 + 1][ar1] = rb1.y;
        Bs[0][ac1 + 2][ar1] = rb1.z; Bs[0][ac1 + 3][ar1] = rb1.w;
    }
    __syncthreads();

    float acc[8][8];
    #pragma unroll
    for (int i = 0; i < 8; i++)
        #pragma unroll
        for (int j = 0; j < 8; j++) acc[i][j] = 0.f;

    const int KT = Kd / 16;
    for (int kt = 0; kt < KT; ++kt) {
        const int cur = kt & 1;
        if (kt + 1 < KT) {
            int k0 = (kt + 1) * 16;
            ra0 = *(const float4*)&Ab[(size_t)ar0 * Kd + k0 + ac0];
            ra1 = *(const float4*)&Ab[(size_t)ar1 * Kd + k0 + ac1];
            int br0 = n0 + ar0, br1 = n0 + ar1;
            rb0 = (br0 < Nd) ? *(const float4*)&g_col[(size_t)br0 * Kd + k0 + ac0]
                             : make_float4(0.f, 0.f, 0.f, 0.f);
            rb1 = (br1 < Nd) ? *(const float4*)&g_col[(size_t)br1 * Kd + k0 + ac1]
                             : make_float4(0.f, 0.f, 0.f, 0.f);
        }
        #pragma unroll
        for (int kk = 0; kk < 16; kk++) {
            float4 a0 = *(const float4*)&As[cur][kk][ty * 8];
            float4 a1 = *(const float4*)&As[cur][kk][ty * 8 + 4];
            float4 b0 = *(const float4*)&Bs[cur][kk][tx * 8];
            float4 b1 = *(const float4*)&Bs[cur][kk][tx * 8 + 4];
            float av[8] = {a0.x, a0.y, a0.z, a0.w, a1.x, a1.y, a1.z, a1.w};
            float bv[8] = {b0.x, b0.y, b0.z, b0.w, b1.x, b1.y, b1.z, b1.w};
            #pragma unroll
            for (int i = 0; i < 8; i++)
                #pragma unroll
                for (int j = 0; j < 8; j++)
                    acc[i][j] += av[i] * bv[j];
        }
        if (kt + 1 < KT) {
            const int nb = cur ^ 1;
            As[nb][ac0 + 0][ar0] = ra0.x; As[nb][ac0 + 1][ar0] = ra0.y;
            As[nb][ac0 + 2][ar0] = ra0.z; As[nb][ac0 + 3][ar0] = ra0.w;
            As[nb][ac1 + 0][ar1] = ra1.x; As[nb][ac1 + 1][ar1] = ra1.y;
            As[nb][ac1 + 2][ar1] = ra1.z; As[nb][ac1 + 3][ar1] = ra1.w;
            Bs[nb][ac0 + 0][ar0] = rb0.x; Bs[nb][ac0 + 1][ar0] = rb0.y;
            Bs[nb][ac0 + 2][ar0] = rb0.z; Bs[nb][ac0 + 3][ar0] = rb0.w;
            Bs[nb][ac1 + 0][ar1] = rb1.x; Bs[nb][ac1 + 1][ar1] = rb1.y;
            Bs[nb][ac1 + 2][ar1] = rb1.z; Bs[nb][ac1 + 3][ar1] = rb1.w;
            __syncthreads();
        }
    }

    #pragma unroll
    for (int i = 0; i < 8; i++) {
        int m = m0 + ty * 8 + i;
        int n = n0 + tx * 8;
        if (n < Nd) {  // Nd % 8 == 0 -> whole 8-chunk valid
            float4* cp = (float4*)&g_P[(size_t)m * Nd + n];
            cp[0] = make_float4(acc[i][0], acc[i][1], acc[i][2], acc[i][3]);
            cp[1] = make_float4(acc[i][4], acc[i][5], acc[i][6], acc[i][7]);
        }
    }
}

// ---------------- gather caps, add bias, squash over 16 -> u ----------------
// grid (c0=256, b=32). Transpose P rows {cap*256+c0} into [16][169] smem tile.
__global__ __launch_bounds__(192) void k_form_u(const float* __restrict__ pbias) {
    __shared__ float tile[NCAP][NPOS];
    const int c0 = blockIdx.x, b = blockIdx.y;
    const int tid = threadIdx.x;
    #pragma unroll
    for (int cap = 0; cap < NCAP; cap++) {
        float bv = pbias[cap * C0 + c0];
        for (int s = tid; s < NPOS; s += 192)
            tile[cap][s] = g_P[((size_t)(cap * C0 + c0)) * NGEMM + b * NPOS + s] + bv;
    }
    __syncthreads();
    for (int s = tid; s < NPOS; s += 192) {
        float v[NCAP];
        float n2 = 0.f;
        #pragma unroll
        for (int cap = 0; cap < NCAP; cap++) {
            v[cap] = tile[cap][s];
            n2 += v[cap] * v[cap];
        }
        float scale = (n2 / (1.f + n2)) / sqrtf(n2 + 1e-8f);
        float4* up = (float4*)(g_u + ((size_t)b * ROUTES + (size_t)c0 * NPOS + s) * NCAP);
        #pragma unroll
        for (int q = 0; q < 4; q++)
            up[q] = make_float4(v[q * 4] * scale, v[q * 4 + 1] * scale,
                                v[q * 4 + 2] * scale, v[q * 4 + 3] * scale);
    }
}

// ---------------- one routing iteration ----------------
// b_log is implicit: b_log[b,j,c] = u_hat[b,j,c,:] . Vacc[b,c,:]
// grid = 256 blocks (169 j each), 256 threads: lane = batch, warp covers all 32 b.
__global__ __launch_bounds__(256) void k_route(const float* __restrict__ W) {
    __shared__ float sv[32 * 41];      // padded Vacc (stride 41: conflict-free)
    __shared__ float ssum[1280];       // per-block partial s [b][c][o]
    const int tid = threadIdx.x;
    for (int i = tid; i < 1280; i += 256) {
        ssum[i] = 0.f;
        sv[(i / 40) * 41 + (i % 40)] = g_vacc[i];
    }
    __syncthreads();

    const int b = tid & 31;
    const int jg = tid >> 5;
    const float* svb = &sv[b * 41];
    const int j0 = blockIdx.x * NPOS;

    float sacc[40];
    #pragma unroll
    for (int i = 0; i < 40; i++) sacc[i] = 0.f;

    for (int jl = jg; jl < NPOS; jl += 8) {
        const int j = j0 + jl;
        const float4* up = (const float4*)(g_u + ((size_t)b * ROUTES + j) * NCAP);
        float4 u0 = up[0], u1 = up[1], u2 = up[2], u3 = up[3];
        float uu[16] = {u0.x, u0.y, u0.z, u0.w, u1.x, u1.y, u1.z, u1.w,
                        u2.x, u2.y, u2.z, u2.w, u3.x, u3.y, u3.z, u3.w};
        const float* Wj = W + (size_t)j * 640;
        float uh[40];
        #pragma unroll
        for (int co = 0; co < 40; co++) {
            const float4* wp = (const float4*)(Wj + co * 16);  // warp-uniform: broadcast
            float4 w0 = wp[0], w1 = wp[1], w2 = wp[2], w3 = wp[3];
            uh[co] = w0.x * uu[0]  + w0.y * uu[1]  + w0.z * uu[2]  + w0.w * uu[3]
                   + w1.x * uu[4]  + w1.y * uu[5]  + w1.z * uu[6]  + w1.w * uu[7]
                   + w2.x * uu[8]  + w2.y * uu[9]  + w2.z * uu[10] + w2.w * uu[11]
                   + w3.x * uu[12] + w3.y * uu[13] + w3.z * uu[14] + w3.w * uu[15];
        }
        float blog[10];
        float mx = -1e30f;
        #pragma unroll
        for (int c = 0; c < 10; c++) {
            float d = uh[c * 4 + 0] * svb[c * 4 + 0] + uh[c * 4 + 1] * svb[c * 4 + 1]
                    + uh[c * 4 + 2] * svb[c * 4 + 2] + uh[c * 4 + 3] * svb[c * 4 + 3];
            blog[c] = d;
            mx = fmaxf(mx, d);
        }
        float sum = 0.f;
        #pragma unroll
        for (int c = 0; c < 10; c++) {
            blog[c] = __expf(blog[c] - mx);
            sum += blog[c];
        }
        float inv = 1.f / sum;
        #pragma unroll
        for (int c = 0; c < 10; c++) {
            float cw = blog[c] * inv;
            sacc[c * 4 + 0] += cw * uh[c * 4 + 0];
            sacc[c * 4 + 1] += cw * uh[c * 4 + 1];
            sacc[c * 4 + 2] += cw * uh[c * 4 + 2];
            sacc[c * 4 + 3] += cw * uh[c * 4 + 3];
        }
    }
    #pragma unroll
    for (int i = 0; i < 40; i++) atomicAdd(&ssum[b * 40 + i], sacc[i]);
    __syncthreads();
    for (int i = tid; i < 1280; i += 256) atomicAdd(&g_s[i], ssum[i]);
}

// ---------------- v = squash(s); Vacc += v; zero s; final softmax on last ----------------
__global__ void k_vupdate(float* __restrict__ out, int last) {
    __shared__ float slen[320];
    const int tid = threadIdx.x;  // 320 = 32 b * 10 cls
    const int b = tid / 10;
    float s0 = g_s[tid * 4 + 0], s1 = g_s[tid * 4 + 1];
    float s2 = g_s[tid * 4 + 2], s3 = g_s[tid * 4 + 3];
    float n2 = s0 * s0 + s1 * s1 + s2 * s2 + s3 * s3;
    float sc = (n2 / (1.f + n2)) / sqrtf(n2 + 1e-8f);
    float v0 = s0 * sc, v1 = s1 * sc, v2 = s2 * sc, v3 = s3 * sc;
    g_vacc[tid * 4 + 0] += v0; g_vacc[tid * 4 + 1] += v1;
    g_vacc[tid * 4 + 2] += v2; g_vacc[tid * 4 + 3] += v3;
    g_s[tid * 4 + 0] = 0.f; g_s[tid * 4 + 1] = 0.f;
    g_s[tid * 4 + 2] = 0.f; g_s[tid * 4 + 3] = 0.f;
    if (last) {
        slen[tid] = sqrtf(v0 * v0 + v1 * v1 + v2 * v2 + v3 * v3);
        __syncthreads();
        float mx = -1e30f;
        for (int c = 0; c < 10; c++) mx = fmaxf(mx, slen[b * 10 + c]);
        float sum = 0.f;
        for (int c = 0; c < 10; c++) sum += expf(slen[b * 10 + c] - mx);
        out[tid] = expf(slen[tid] - mx) / sum;
    }
}

// ---------------- launch ----------------
extern "C" void kernel_launch(void* const* d_in, const int* in_sizes, int n_in,
                              void* d_out, int out_size) {
    const float* x       = (const float*)d_in[0];
    const float* conv_w  = (const float*)d_in[1];
    const float* conv_b  = (const float*)d_in[2];
    const float* pcaps_w = (const float*)d_in[3];
    const float* pcaps_b = (const float*)d_in[4];
    const float* route_W = (const float*)d_in[5];
    float* out = (float*)d_out;
    (void)in_sizes; (void)n_in; (void)out_size;

    k_zero<<<1, 256>>>();
    k_conv1<<<dim3(8, 32), 256>>>(x, conv_w, conv_b);
    k_im2col<<<NGEMM, 256>>>();
    k_sgemm<<<dim3((NGEMM + 127) / 128, OC2 / 128), 256>>>(pcaps_w);
    k_form_u<<<dim3(C0, B_), 192>>>(pcaps_b);
    for (int t = 0; t < 8; t++) {
        k_route<<<ROUTES / NPOS, 256>>>(route_W);
        k_vupdate<<<1, 320>>>(out, t == 7);
    }
}

// round 6
// speedup vs baseline: 1.8168x; 1.8168x over previous
#include <cuda_runtime.h>
#include <cuda_bf16.h>
#include <math.h>
#include <stdint.h>
#include <stddef.h>

// ---------------- problem constants ----------------
#define B_      32
#define CIN     3
#define HIN     32
#define C0      256
#define HO      29          // conv1 output spatial
#define NCAP    16
#define OC2     4096        // NCAP*C0
#define SO      13          // pcaps output spatial
#define NPOS    169         // 13*13
#define ROUTES  43264       // C0*NPOS
#define NCLS    10
#define OD      4
#define NGEMM   5408        // B_*NPOS
#define KGEMM   4096        // C0*16
#define NPAD    5632        // 44 * 128

// GEMM tiling
#define M_TILE   128
#define N_TILE   128
#define K_STAGE  64                  // bf16 elems per stage (128B rows)
#define NSTAGES  192                 // 3 passes * (4096/64)
#define SM_BUF   32768               // 16KB A + 16KB B per stage
#define SMEM_DYN (1024 + 3 * SM_BUF)

// ---------------- scratch (static device memory; no allocations) ----------------
__device__ float g_h[B_ * C0 * HO * HO];                       // stem conv out
__device__ __nv_bfloat16 g_Ah[(size_t)OC2 * KGEMM];            // pcaps_w hi
__device__ __nv_bfloat16 g_Al[(size_t)OC2 * KGEMM];            // pcaps_w lo
__device__ __nv_bfloat16 g_Bh[(size_t)NPAD * KGEMM];           // im2col hi (padded)
__device__ __nv_bfloat16 g_Bl[(size_t)NPAD * KGEMM];           // im2col lo (padded)
__device__ float g_P[(size_t)OC2 * NGEMM];                     // pcaps conv out [oc][n]
__device__ float g_u[(size_t)B_ * ROUTES * NCAP];              // squashed capsules
__device__ float g_s[B_ * NCLS * OD];                          // routing accumulator
__device__ float g_vacc[B_ * NCLS * OD];                       // sum of v_t (implicit b_log)

// ---------------- helpers ----------------
__device__ __forceinline__ uint32_t smem_u32(const void* p) {
    uint32_t a;
    asm("{ .reg .u64 t; cvta.to.shared.u64 t, %1; cvt.u32.u64 %0, t; }" : "=r"(a) : "l"(p));
    return a;
}
__device__ __forceinline__ void cpa16(uint32_t dst, const void* src) {
    asm volatile("cp.async.cg.shared.global [%0], [%1], 16;" :: "r"(dst), "l"(src) : "memory");
}
#define CPA_COMMIT() asm volatile("cp.async.commit_group;" ::: "memory")
#define SW128(o) ((o) ^ (((o) >> 3) & 0x70))

#define LDSM_X4(r0, r1, r2, r3, addr)                                              \
    asm volatile("ldmatrix.sync.aligned.m8n8.x4.shared.b16 {%0,%1,%2,%3}, [%4];"  \
        : "=r"(r0), "=r"(r1), "=r"(r2), "=r"(r3) : "r"(addr))

#define MMA16816(d, a, b0v, b1v)                                                   \
    asm volatile("mma.sync.aligned.m16n8k16.row.col.f32.bf16.bf16.f32 "           \
        "{%0,%1,%2,%3},{%4,%5,%6,%7},{%8,%9},{%0,%1,%2,%3};"                      \
        : "+f"((d)[0]), "+f"((d)[1]), "+f"((d)[2]), "+f"((d)[3])                   \
        : "r"((a)[0]), "r"((a)[1]), "r"((a)[2]), "r"((a)[3]), "r"(b0v), "r"(b1v))

// ---------------- init: zero the tiny routing state ----------------
__global__ void k_zero() {
    for (int i = threadIdx.x; i < B_ * NCLS * OD; i += blockDim.x) {
        g_s[i] = 0.f;
        g_vacc[i] = 0.f;
    }
}

// ---------------- stem conv 4x4 stride 1 + relu ----------------
__global__ __launch_bounds__(256) void k_conv1(const float* __restrict__ x,
                                               const float* __restrict__ w,
                                               const float* __restrict__ bias) {
    __shared__ float simg[CIN * HIN * HIN];
    __shared__ float swt[32 * CIN * 16];
    __shared__ float sb[32];
    const int b = blockIdx.y, ocg = blockIdx.x;
    const int tid = threadIdx.x;

    for (int i = tid; i < CIN * HIN * HIN; i += 256)
        simg[i] = x[b * CIN * HIN * HIN + i];
    for (int i = tid; i < 32 * 48; i += 256)
        swt[i] = w[(ocg * 32) * 48 + i];
    if (tid < 32) sb[tid] = bias[ocg * 32 + tid];
    __syncthreads();

    for (int it = tid; it < 32 * 29 * 8; it += 256) {
        int oc = it / (29 * 8);
        int r  = it % (29 * 8);
        int p  = r >> 3;
        int qb = (r & 7) * 4;
        float a0 = sb[oc], a1 = a0, a2 = a0, a3 = a0;
        #pragma unroll
        for (int ic = 0; ic < CIN; ic++) {
            #pragma unroll
            for (int ky = 0; ky < 4; ky++) {
                const float* rp = &simg[ic * 1024 + (p + ky) * 32 + qb];
                const float* wp = &swt[oc * 48 + ic * 16 + ky * 4];
                float r0 = rp[0], r1 = rp[1], r2 = rp[2], r3 = rp[3];
                float r4 = (qb + 4 < 32) ? rp[4] : 0.f;
                float r5 = (qb + 5 < 32) ? rp[5] : 0.f;
                float r6 = (qb + 6 < 32) ? rp[6] : 0.f;
                float w0 = wp[0], w1 = wp[1], w2 = wp[2], w3 = wp[3];
                a0 += r0 * w0 + r1 * w1 + r2 * w2 + r3 * w3;
                a1 += r1 * w0 + r2 * w1 + r3 * w2 + r4 * w3;
                a2 += r2 * w0 + r3 * w1 + r4 * w2 + r5 * w3;
                a3 += r3 * w0 + r4 * w1 + r5 * w2 + r6 * w3;
            }
        }
        size_t base = (((size_t)b * C0 + ocg * 32 + oc) * HO + p) * HO;
        if (qb + 0 < HO) g_h[base + qb + 0] = fmaxf(a0, 0.f);
        if (qb + 1 < HO) g_h[base + qb + 1] = fmaxf(a1, 0.f);
        if (qb + 2 < HO) g_h[base + qb + 2] = fmaxf(a2, 0.f);
        if (qb + 3 < HO) g_h[base + qb + 3] = fmaxf(a3, 0.f);
    }
}

// ---------------- split pcaps_w into bf16 hi/lo ----------------
__global__ __launch_bounds__(256) void k_splitW(const float* __restrict__ A) {
    size_t i = (size_t)blockIdx.x * 256 + threadIdx.x;
    size_t stride = (size_t)gridDim.x * 256;
    size_t total = (size_t)OC2 * KGEMM;
    for (; i < total; i += stride) {
        float v = A[i];
        __nv_bfloat16 h = __float2bfloat16(v);
        float lo = v - __bfloat162float(h);
        g_Ah[i] = h;
        g_Al[i] = __float2bfloat16(lo);
    }
}

// ---------------- fused im2col + bf16 hi/lo split (writes padded B) ----------------
__global__ void k_im2col_split() {
    const int n = blockIdx.x;
    const size_t ob = (size_t)n * KGEMM;
    if (n >= NGEMM) {
        for (int k = threadIdx.x; k < KGEMM; k += blockDim.x) {
            g_Bh[ob + k] = __float2bfloat16(0.f);
            g_Bl[ob + k] = __float2bfloat16(0.f);
        }
        return;
    }
    const int b = n / NPOS, s = n % NPOS;
    const int y = s / SO, xq = s % SO;
    for (int k = threadIdx.x; k < KGEMM; k += blockDim.x) {
        int ic = k >> 4, kp = k & 15;
        int ky = kp >> 2, kx = kp & 3;
        float v = g_h[(((size_t)b * C0 + ic) * HO + 2 * y + ky) * HO + 2 * xq + kx];
        __nv_bfloat16 h = __float2bfloat16(v);
        g_Bh[ob + k] = h;
        g_Bl[ob + k] = __float2bfloat16(v - __bfloat162float(h));
    }
}

// ---------------- bf16 mma.sync GEMM: P[m][n] = sum_k A[m][k]*B[n][k] ----------------
// 3-pass hi/lo split accumulated in fp32 registers across all 192 K-stages.
// 128x128 CTA tile, 8 warps (4m x 2n), warp tile 32x64, mma.m16n8k16.
__global__ __launch_bounds__(256, 1) void k_gemm_mma() {
    extern __shared__ __align__(16) char dsm[];
    const uint32_t sbase = smem_u32(dsm);
    const uint32_t tiles = (sbase + 1023) & ~1023u;
    const int tid = threadIdx.x;
    const int lane = tid & 31;
    const int wid = tid >> 5;
    const int wm = wid & 3;            // 0..3 (m)
    const int wn = wid >> 2;           // 0..1 (n)
    const int m0 = blockIdx.y * M_TILE;
    const int n0 = blockIdx.x * N_TILE;

    auto load_stage = [&](int s) {
        const int p = s >> 6;
        const size_t koff = (size_t)(s & 63) * (K_STAGE * 2);   // bytes
        const __nv_bfloat16* A = (p == 2) ? g_Al : g_Ah;
        const __nv_bfloat16* B = (p == 1) ? g_Bl : g_Bh;
        const char* Ab = (const char*)A + (size_t)m0 * (KGEMM * 2) + koff;
        const char* Bb = (const char*)B + (size_t)n0 * (KGEMM * 2) + koff;
        const uint32_t abase = tiles + (s % 3) * SM_BUF;
        const uint32_t bbase = abase + 16384;
        #pragma unroll
        for (int i = 0; i < 4; i++) {      // A: 128 rows x 8 x 16B
            int id = tid + i * 256;
            int r = id >> 3, c = id & 7;
            cpa16(abase + SW128(r * 128 + c * 16), Ab + (size_t)r * (KGEMM * 2) + c * 16);
        }
        #pragma unroll
        for (int i = 0; i < 4; i++) {      // B: 128 rows x 8 x 16B
            int id = tid + i * 256;
            int r = id >> 3, c = id & 7;
            cpa16(bbase + SW128(r * 128 + c * 16), Bb + (size_t)r * (KGEMM * 2) + c * 16);
        }
        CPA_COMMIT();
    };

    float d[2][8][4];
    #pragma unroll
    for (int i = 0; i < 2; i++)
        #pragma unroll
        for (int j = 0; j < 8; j++)
            #pragma unroll
            for (int q = 0; q < 4; q++) d[i][j][q] = 0.f;

    // ldmatrix lane-address row/col components (byte offsets within tile)
    const int a_row0 = wm * 32 + (lane & 15);          // + mf*16
    const int a_colh = (lane >> 4) * 16;               // k half within 16-chunk
    const int b_row0 = wn * 64 + (lane & 7) + ((lane >> 4) & 1) * 8;   // + nf*16
    const int b_colh = ((lane >> 3) & 1) * 16;

    load_stage(0);
    load_stage(1);

    for (int s = 0; s < NSTAGES; s++) {
        if (s + 2 < NSTAGES) {
            asm volatile("cp.async.wait_group 1;" ::: "memory");
        } else {
            asm volatile("cp.async.wait_group 0;" ::: "memory");
        }
        __syncthreads();
        if (s + 2 < NSTAGES) load_stage(s + 2);

        const uint32_t abase = tiles + (s % 3) * SM_BUF;
        const uint32_t bbase = abase + 16384;

        #pragma unroll
        for (int kk = 0; kk < 4; kk++) {
            const int kbyte = kk * 32;
            uint32_t a[2][4];
            #pragma unroll
            for (int mf = 0; mf < 2; mf++) {
                uint32_t off = (a_row0 + mf * 16) * 128 + kbyte + a_colh;
                LDSM_X4(a[mf][0], a[mf][1], a[mf][2], a[mf][3], abase + SW128(off));
            }
            #pragma unroll
            for (int nf = 0; nf < 4; nf++) {
                uint32_t b0, b1, b2, b3;
                uint32_t off = (b_row0 + nf * 16) * 128 + kbyte + b_colh;
                LDSM_X4(b0, b1, b2, b3, bbase + SW128(off));
                MMA16816(d[0][nf * 2 + 0], a[0], b0, b1);
                MMA16816(d[0][nf * 2 + 1], a[0], b2, b3);
                MMA16816(d[1][nf * 2 + 0], a[1], b0, b1);
                MMA16816(d[1][nf * 2 + 1], a[1], b2, b3);
            }
        }
    }

    // epilogue: d[mf][nf] -> C rows m0+wm*32+mf*16+{lane/4, lane/4+8},
    //                         cols n0+wn*64+nf*8+(lane%4)*2 {+0,+1}
    const int er = lane >> 2;
    const int ec = (lane & 3) * 2;
    #pragma unroll
    for (int mf = 0; mf < 2; mf++) {
        #pragma unroll
        for (int nf = 0; nf < 8; nf++) {
            int r = m0 + wm * 32 + mf * 16 + er;
            int c = n0 + wn * 64 + nf * 8 + ec;
            if (c < NGEMM) {
                float2* p0 = (float2*)&g_P[(size_t)r * NGEMM + c];
                *p0 = make_float2(d[mf][nf][0], d[mf][nf][1]);
                float2* p1 = (float2*)&g_P[(size_t)(r + 8) * NGEMM + c];
                *p1 = make_float2(d[mf][nf][2], d[mf][nf][3]);
            }
        }
    }
}

// ---------------- gather caps, add bias, squash over 16 -> u ----------------
__global__ __launch_bounds__(192) void k_form_u(const float* __restrict__ pbias) {
    __shared__ float tile[NCAP][NPOS];
    const int c0 = blockIdx.x, b = blockIdx.y;
    const int tid = threadIdx.x;
    #pragma unroll
    for (int cap = 0; cap < NCAP; cap++) {
        float bv = pbias[cap * C0 + c0];
        for (int s = tid; s < NPOS; s += 192)
            tile[cap][s] = g_P[((size_t)(cap * C0 + c0)) * NGEMM + b * NPOS + s] + bv;
    }
    __syncthreads();
    for (int s = tid; s < NPOS; s += 192) {
        float v[NCAP];
        float n2 = 0.f;
        #pragma unroll
        for (int cap = 0; cap < NCAP; cap++) {
            v[cap] = tile[cap][s];
            n2 += v[cap] * v[cap];
        }
        float scale = (n2 / (1.f + n2)) / sqrtf(n2 + 1e-8f);
        float4* up = (float4*)(g_u + ((size_t)b * ROUTES + (size_t)c0 * NPOS + s) * NCAP);
        #pragma unroll
        for (int q = 0; q < 4; q++)
            up[q] = make_float4(v[q * 4] * scale, v[q * 4 + 1] * scale,
                                v[q * 4 + 2] * scale, v[q * 4 + 3] * scale);
    }
}

// ---------------- one routing iteration ----------------
__global__ __launch_bounds__(256) void k_route(const float* __restrict__ W) {
    __shared__ float sv[32 * 41];
    __shared__ float ssum[1280];
    const int tid = threadIdx.x;
    for (int i = tid; i < 1280; i += 256) {
        ssum[i] = 0.f;
        sv[(i / 40) * 41 + (i % 40)] = g_vacc[i];
    }
    __syncthreads();

    const int b = tid & 31;
    const int jg = tid >> 5;
    const float* svb = &sv[b * 41];
    const int j0 = blockIdx.x * NPOS;

    float sacc[40];
    #pragma unroll
    for (int i = 0; i < 40; i++) sacc[i] = 0.f;

    for (int jl = jg; jl < NPOS; jl += 8) {
        const int j = j0 + jl;
        const float4* up = (const float4*)(g_u + ((size_t)b * ROUTES + j) * NCAP);
        float4 u0 = up[0], u1 = up[1], u2 = up[2], u3 = up[3];
        float uu[16] = {u0.x, u0.y, u0.z, u0.w, u1.x, u1.y, u1.z, u1.w,
                        u2.x, u2.y, u2.z, u2.w, u3.x, u3.y, u3.z, u3.w};
        const float* Wj = W + (size_t)j * 640;
        float uh[40];
        #pragma unroll
        for (int co = 0; co < 40; co++) {
            const float4* wp = (const float4*)(Wj + co * 16);
            float4 w0 = wp[0], w1 = wp[1], w2 = wp[2], w3 = wp[3];
            uh[co] = w0.x * uu[0]  + w0.y * uu[1]  + w0.z * uu[2]  + w0.w * uu[3]
                   + w1.x * uu[4]  + w1.y * uu[5]  + w1.z * uu[6]  + w1.w * uu[7]
                   + w2.x * uu[8]  + w2.y * uu[9]  + w2.z * uu[10] + w2.w * uu[11]
                   + w3.x * uu[12] + w3.y * uu[13] + w3.z * uu[14] + w3.w * uu[15];
        }
        float blog[10];
        float mx = -1e30f;
        #pragma unroll
        for (int c = 0; c < 10; c++) {
            float dd = uh[c * 4 + 0] * svb[c * 4 + 0] + uh[c * 4 + 1] * svb[c * 4 + 1]
                     + uh[c * 4 + 2] * svb[c * 4 + 2] + uh[c * 4 + 3] * svb[c * 4 + 3];
            blog[c] = dd;
            mx = fmaxf(mx, dd);
        }
        float sum = 0.f;
        #pragma unroll
        for (int c = 0; c < 10; c++) {
            blog[c] = __expf(blog[c] - mx);
            sum += blog[c];
        }
        float inv = 1.f / sum;
        #pragma unroll
        for (int c = 0; c < 10; c++) {
            float cw = blog[c] * inv;
            sacc[c * 4 + 0] += cw * uh[c * 4 + 0];
            sacc[c * 4 + 1] += cw * uh[c * 4 + 1];
            sacc[c * 4 + 2] += cw * uh[c * 4 + 2];
            sacc[c * 4 + 3] += cw * uh[c * 4 + 3];
        }
    }
    #pragma unroll
    for (int i = 0; i < 40; i++) atomicAdd(&ssum[b * 40 + i], sacc[i]);
    __syncthreads();
    for (int i = tid; i < 1280; i += 256) atomicAdd(&g_s[i], ssum[i]);
}

// ---------------- v = squash(s); Vacc += v; zero s; final softmax on last ----------------
__global__ void k_vupdate(float* __restrict__ out, int last) {
    __shared__ float slen[320];
    const int tid = threadIdx.x;
    const int b = tid / 10;
    float s0 = g_s[tid * 4 + 0], s1 = g_s[tid * 4 + 1];
    float s2 = g_s[tid * 4 + 2], s3 = g_s[tid * 4 + 3];
    float n2 = s0 * s0 + s1 * s1 + s2 * s2 + s3 * s3;
    float sc = (n2 / (1.f + n2)) / sqrtf(n2 + 1e-8f);
    float v0 = s0 * sc, v1 = s1 * sc, v2 = s2 * sc, v3 = s3 * sc;
    g_vacc[tid * 4 + 0] += v0; g_vacc[tid * 4 + 1] += v1;
    g_vacc[tid * 4 + 2] += v2; g_vacc[tid * 4 + 3] += v3;
    g_s[tid * 4 + 0] = 0.f; g_s[tid * 4 + 1] = 0.f;
    g_s[tid * 4 + 2] = 0.f; g_s[tid * 4 + 3] = 0.f;
    if (last) {
        slen[tid] = sqrtf(v0 * v0 + v1 * v1 + v2 * v2 + v3 * v3);
        __syncthreads();
        float mx = -1e30f;
        for (int c = 0; c < 10; c++) mx = fmaxf(mx, slen[b * 10 + c]);
        float sum = 0.f;
        for (int c = 0; c < 10; c++) sum += expf(slen[b * 10 + c] - mx);
        out[tid] = expf(slen[tid] - mx) / sum;
    }
}

// ---------------- launch ----------------
extern "C" void kernel_launch(void* const* d_in, const int* in_sizes, int n_in,
                              void* d_out, int out_size) {
    const float* x       = (const float*)d_in[0];
    const float* conv_w  = (const float*)d_in[1];
    const float* conv_b  = (const float*)d_in[2];
    const float* pcaps_w = (const float*)d_in[3];
    const float* pcaps_b = (const float*)d_in[4];
    const float* route_W = (const float*)d_in[5];
    float* out = (float*)d_out;
    (void)in_sizes; (void)n_in; (void)out_size;

    cudaFuncSetAttribute(k_gemm_mma, cudaFuncAttributeMaxDynamicSharedMemorySize, SMEM_DYN);

    k_zero<<<1, 256>>>();
    k_conv1<<<dim3(8, 32), 256>>>(x, conv_w, conv_b);
    k_splitW<<<2048, 256>>>(pcaps_w);
    k_im2col_split<<<NPAD, 256>>>();
    k_gemm_mma<<<dim3(NPAD / N_TILE, OC2 / M_TILE), 256, SMEM_DYN>>>();
    k_form_u<<<dim3(C0, B_), 192>>>(pcaps_b);
    for (int t = 0; t < 8; t++) {
        k_route<<<ROUTES / NPOS, 256>>>(route_W);
        k_vupdate<<<1, 320>>>(out, t == 7);
    }
}

// round 8
// speedup vs baseline: 2.6034x; 1.4330x over previous
#include <cuda_runtime.h>
#include <cuda_bf16.h>
#include <math.h>
#include <stdint.h>
#include <stddef.h>

// ---------------- problem constants ----------------
#define B_      32
#define CIN     3
#define HIN     32
#define C0      256
#define HO      29          // conv1 output spatial
#define NCAP    16
#define OC2     4096        // NCAP*C0
#define SO      13          // pcaps output spatial
#define NPOS    169         // 13*13
#define ROUTES  43264       // C0*NPOS
#define NCLS    10
#define OD      4
#define NGEMM   5408        // B_*NPOS
#define KGEMM   4096        // C0*16
#define NPAD    5632        // 44 * 128

// GEMM tiling
#define M_TILE   128
#define N_TILE   128
#define K_STAGE  64                  // bf16 elems per stage (128B rows)
#define NSTAGES  64                  // single bf16 pass: 4096/64
#define SM_BUF   32768               // 16KB A + 16KB B per stage
#define SMEM_DYN (1024 + 3 * SM_BUF)

// ---------------- scratch (static device memory; no allocations) ----------------
__device__ float g_h[B_ * C0 * HO * HO];                       // stem conv out
__device__ __nv_bfloat16 g_Ah[(size_t)OC2 * KGEMM];            // pcaps_w bf16
__device__ __nv_bfloat16 g_Bh[(size_t)NPAD * KGEMM];           // im2col bf16 (padded)
__device__ float g_P[(size_t)OC2 * NGEMM];                     // pcaps conv out [oc][n]
__device__ float g_u[(size_t)B_ * ROUTES * NCAP];              // squashed capsules
__device__ float g_s[B_ * NCLS * OD];                          // routing accumulator
__device__ float g_vacc[B_ * NCLS * OD];                       // sum of v_t (implicit b_log)

// ---------------- helpers ----------------
__device__ __forceinline__ uint32_t smem_u32(const void* p) {
    uint32_t a;
    asm("{ .reg .u64 t; cvta.to.shared.u64 t, %1; cvt.u32.u64 %0, t; }" : "=r"(a) : "l"(p));
    return a;
}
__device__ __forceinline__ void cpa16(uint32_t dst, const void* src) {
    asm volatile("cp.async.cg.shared.global [%0], [%1], 16;" :: "r"(dst), "l"(src) : "memory");
}
#define CPA_COMMIT() asm volatile("cp.async.commit_group;" ::: "memory")
#define SW128(o) ((o) ^ (((o) >> 3) & 0x70))

#define LDSM_X4(r0, r1, r2, r3, addr)                                              \
    asm volatile("ldmatrix.sync.aligned.m8n8.x4.shared.b16 {%0,%1,%2,%3}, [%4];"  \
        : "=r"(r0), "=r"(r1), "=r"(r2), "=r"(r3) : "r"(addr))

#define MMA16816(d, a, b0v, b1v)                                                   \
    asm volatile("mma.sync.aligned.m16n8k16.row.col.f32.bf16.bf16.f32 "           \
        "{%0,%1,%2,%3},{%4,%5,%6,%7},{%8,%9},{%0,%1,%2,%3};"                      \
        : "+f"((d)[0]), "+f"((d)[1]), "+f"((d)[2]), "+f"((d)[3])                   \
        : "r"((a)[0]), "r"((a)[1]), "r"((a)[2]), "r"((a)[3]), "r"(b0v), "r"(b1v))

// ---------------- init: zero the tiny routing state ----------------
__global__ void k_zero() {
    for (int i = threadIdx.x; i < B_ * NCLS * OD; i += blockDim.x) {
        g_s[i] = 0.f;
        g_vacc[i] = 0.f;
    }
}

// ---------------- stem conv 4x4 stride 1 + relu ----------------
__global__ __launch_bounds__(256) void k_conv1(const float* __restrict__ x,
                                               const float* __restrict__ w,
                                               const float* __restrict__ bias) {
    __shared__ float simg[CIN * HIN * HIN];
    __shared__ float swt[32 * CIN * 16];
    __shared__ float sb[32];
    const int b = blockIdx.y, ocg = blockIdx.x;
    const int tid = threadIdx.x;

    for (int i = tid; i < CIN * HIN * HIN; i += 256)
        simg[i] = x[b * CIN * HIN * HIN + i];
    for (int i = tid; i < 32 * 48; i += 256)
        swt[i] = w[(ocg * 32) * 48 + i];
    if (tid < 32) sb[tid] = bias[ocg * 32 + tid];
    __syncthreads();

    for (int it = tid; it < 32 * 29 * 8; it += 256) {
        int oc = it / (29 * 8);
        int r  = it % (29 * 8);
        int p  = r >> 3;
        int qb = (r & 7) * 4;
        float a0 = sb[oc], a1 = a0, a2 = a0, a3 = a0;
        #pragma unroll
        for (int ic = 0; ic < CIN; ic++) {
            #pragma unroll
            for (int ky = 0; ky < 4; ky++) {
                const float* rp = &simg[ic * 1024 + (p + ky) * 32 + qb];
                const float* wp = &swt[oc * 48 + ic * 16 + ky * 4];
                float r0 = rp[0], r1 = rp[1], r2 = rp[2], r3 = rp[3];
                float r4 = (qb + 4 < 32) ? rp[4] : 0.f;
                float r5 = (qb + 5 < 32) ? rp[5] : 0.f;
                float r6 = (qb + 6 < 32) ? rp[6] : 0.f;
                float w0 = wp[0], w1 = wp[1], w2 = wp[2], w3 = wp[3];
                a0 += r0 * w0 + r1 * w1 + r2 * w2 + r3 * w3;
                a1 += r1 * w0 + r2 * w1 + r3 * w2 + r4 * w3;
                a2 += r2 * w0 + r3 * w1 + r4 * w2 + r5 * w3;
                a3 += r3 * w0 + r4 * w1 + r5 * w2 + r6 * w3;
            }
        }
        size_t base = (((size_t)b * C0 + ocg * 32 + oc) * HO + p) * HO;
        if (qb + 0 < HO) g_h[base + qb + 0] = fmaxf(a0, 0.f);
        if (qb + 1 < HO) g_h[base + qb + 1] = fmaxf(a1, 0.f);
        if (qb + 2 < HO) g_h[base + qb + 2] = fmaxf(a2, 0.f);
        if (qb + 3 < HO) g_h[base + qb + 3] = fmaxf(a3, 0.f);
    }
}

// ---------------- convert pcaps_w to bf16 ----------------
__global__ __launch_bounds__(256) void k_cvtW(const float* __restrict__ A) {
    size_t i = (size_t)blockIdx.x * 256 + threadIdx.x;
    size_t stride = (size_t)gridDim.x * 256;
    size_t total = (size_t)OC2 * KGEMM;
    for (; i < total; i += stride)
        g_Ah[i] = __float2bfloat16(A[i]);
}

// ---------------- fused im2col + bf16 convert (writes padded B) ----------------
// B[n][k], n = b*169 + y*13 + x, k = ic*16 + ky*4 + kx; rows >= NGEMM zeroed.
__global__ void k_im2col_cvt() {
    const int n = blockIdx.x;
    const size_t ob = (size_t)n * KGEMM;
    if (n >= NGEMM) {
        for (int k = threadIdx.x; k < KGEMM; k += blockDim.x)
            g_Bh[ob + k] = __float2bfloat16(0.f);
        return;
    }
    const int b = n / NPOS, s = n % NPOS;
    const int y = s / SO, xq = s % SO;
    for (int k = threadIdx.x; k < KGEMM; k += blockDim.x) {
        int ic = k >> 4, kp = k & 15;
        int ky = kp >> 2, kx = kp & 3;
        float v = g_h[(((size_t)b * C0 + ic) * HO + 2 * y + ky) * HO + 2 * xq + kx];
        g_Bh[ob + k] = __float2bfloat16(v);
    }
}

// ---------------- bf16 mma.sync GEMM: P[m][n] = sum_k A[m][k]*B[n][k] ----------------
// single bf16 pass, fp32 accum. 128x128 CTA tile, 8 warps (4m x 2n),
// warp tile 32x64, mma.m16n8k16, 3-stage cp.async ring.
__global__ __launch_bounds__(256, 1) void k_gemm_mma() {
    extern __shared__ __align__(16) char dsm[];
    const uint32_t sbase = smem_u32(dsm);
    const uint32_t tiles = (sbase + 1023) & ~1023u;
    const int tid = threadIdx.x;
    const int lane = tid & 31;
    const int wid = tid >> 5;
    const int wm = wid & 3;            // 0..3 (m)
    const int wn = wid >> 2;           // 0..1 (n)
    const int m0 = blockIdx.y * M_TILE;
    const int n0 = blockIdx.x * N_TILE;

    auto load_stage = [&](int s) {
        const size_t koff = (size_t)s * (K_STAGE * 2);          // bytes
        const char* Ab = (const char*)g_Ah + (size_t)m0 * (KGEMM * 2) + koff;
        const char* Bb = (const char*)g_Bh + (size_t)n0 * (KGEMM * 2) + koff;
        const uint32_t abase = tiles + (s % 3) * SM_BUF;
        const uint32_t bbase = abase + 16384;
        #pragma unroll
        for (int i = 0; i < 4; i++) {      // A: 128 rows x 8 x 16B
            int id = tid + i * 256;
            int r = id >> 3, c = id & 7;
            cpa16(abase + SW128(r * 128 + c * 16), Ab + (size_t)r * (KGEMM * 2) + c * 16);
        }
        #pragma unroll
        for (int i = 0; i < 4; i++) {      // B: 128 rows x 8 x 16B
            int id = tid + i * 256;
            int r = id >> 3, c = id & 7;
            cpa16(bbase + SW128(r * 128 + c * 16), Bb + (size_t)r * (KGEMM * 2) + c * 16);
        }
        CPA_COMMIT();
    };

    float d[2][8][4];
    #pragma unroll
    for (int i = 0; i < 2; i++)
        #pragma unroll
        for (int j = 0; j < 8; j++)
            #pragma unroll
            for (int q = 0; q < 4; q++) d[i][j][q] = 0.f;

    // ldmatrix lane-address row/col components (byte offsets within tile)
    const int a_row0 = wm * 32 + (lane & 15);          // + mf*16
    const int a_colh = (lane >> 4) * 16;               // k half within 16-chunk
    const int b_row0 = wn * 64 + (lane & 7) + ((lane >> 4) & 1) * 8;   // + nf*16
    const int b_colh = ((lane >> 3) & 1) * 16;

    load_stage(0);
    load_stage(1);

    for (int s = 0; s < NSTAGES; s++) {
        if (s + 2 < NSTAGES) {
            asm volatile("cp.async.wait_group 1;" ::: "memory");
        } else {
            asm volatile("cp.async.wait_group 0;" ::: "memory");
        }
        __syncthreads();
        if (s + 2 < NSTAGES) load_stage(s + 2);

        const uint32_t abase = tiles + (s % 3) * SM_BUF;
        const uint32_t bbase = abase + 16384;

        #pragma unroll
        for (int kk = 0; kk < 4; kk++) {
            const int kbyte = kk * 32;
            uint32_t a[2][4];
            #pragma unroll
            for (int mf = 0; mf < 2; mf++) {
                uint32_t off = (a_row0 + mf * 16) * 128 + kbyte + a_colh;
                LDSM_X4(a[mf][0], a[mf][1], a[mf][2], a[mf][3], abase + SW128(off));
            }
            #pragma unroll
            for (int nf = 0; nf < 4; nf++) {
                uint32_t b0, b1, b2, b3;
                uint32_t off = (b_row0 + nf * 16) * 128 + kbyte + b_colh;
                LDSM_X4(b0, b1, b2, b3, bbase + SW128(off));
                MMA16816(d[0][nf * 2 + 0], a[0], b0, b1);
                MMA16816(d[0][nf * 2 + 1], a[0], b2, b3);
                MMA16816(d[1][nf * 2 + 0], a[1], b0, b1);
                MMA16816(d[1][nf * 2 + 1], a[1], b2, b3);
            }
        }
    }

    // epilogue: d[mf][nf] -> C rows m0+wm*32+mf*16+{lane/4, lane/4+8},
    //                         cols n0+wn*64+nf*8+(lane%4)*2 {+0,+1}
    const int er = lane >> 2;
    const int ec = (lane & 3) * 2;
    #pragma unroll
    for (int mf = 0; mf < 2; mf++) {
        #pragma unroll
        for (int nf = 0; nf < 8; nf++) {
            int r = m0 + wm * 32 + mf * 16 + er;
            int c = n0 + wn * 64 + nf * 8 + ec;
            if (c < NGEMM) {
                float2* p0 = (float2*)&g_P[(size_t)r * NGEMM + c];
                *p0 = make_float2(d[mf][nf][0], d[mf][nf][1]);
                float2* p1 = (float2*)&g_P[(size_t)(r + 8) * NGEMM + c];
                *p1 = make_float2(d[mf][nf][2], d[mf][nf][3]);
            }
        }
    }
}

// ---------------- gather caps, add bias, squash over 16 -> u ----------------
__global__ __launch_bounds__(192) void k_form_u(const float* __restrict__ pbias) {
    __shared__ float tile[NCAP][NPOS];
    const int c0 = blockIdx.x, b = blockIdx.y;
    const int tid = threadIdx.x;
    #pragma unroll
    for (int cap = 0; cap < NCAP; cap++) {
        float bv = pbias[cap * C0 + c0];
        for (int s = tid; s < NPOS; s += 192)
            tile[cap][s] = g_P[((size_t)(cap * C0 + c0)) * NGEMM + b * NPOS + s] + bv;
    }
    __syncthreads();
    for (int s = tid; s < NPOS; s += 192) {
        float v[NCAP];
        float n2 = 0.f;
        #pragma unroll
        for (int cap = 0; cap < NCAP; cap++) {
            v[cap] = tile[cap][s];
            n2 += v[cap] * v[cap];
        }
        float scale = (n2 / (1.f + n2)) / sqrtf(n2 + 1e-8f);
        float4* up = (float4*)(g_u + ((size_t)b * ROUTES + (size_t)c0 * NPOS + s) * NCAP);
        #pragma unroll
        for (int q = 0; q < 4; q++)
            up[q] = make_float4(v[q * 4] * scale, v[q * 4 + 1] * scale,
                                v[q * 4 + 2] * scale, v[q * 4 + 3] * scale);
    }
}

// ---------------- one routing iteration ----------------
__global__ __launch_bounds__(256) void k_route(const float* __restrict__ W) {
    __shared__ float sv[32 * 41];
    __shared__ float ssum[1280];
    const int tid = threadIdx.x;
    for (int i = tid; i < 1280; i += 256) {
        ssum[i] = 0.f;
        sv[(i / 40) * 41 + (i % 40)] = g_vacc[i];
    }
    __syncthreads();

    const int b = tid & 31;
    const int jg = tid >> 5;
    const float* svb = &sv[b * 41];
    const int j0 = blockIdx.x * NPOS;

    float sacc[40];
    #pragma unroll
    for (int i = 0; i < 40; i++) sacc[i] = 0.f;

    for (int jl = jg; jl < NPOS; jl += 8) {
        const int j = j0 + jl;
        const float4* up = (const float4*)(g_u + ((size_t)b * ROUTES + j) * NCAP);
        float4 u0 = up[0], u1 = up[1], u2 = up[2], u3 = up[3];
        float uu[16] = {u0.x, u0.y, u0.z, u0.w, u1.x, u1.y, u1.z, u1.w,
                        u2.x, u2.y, u2.z, u2.w, u3.x, u3.y, u3.z, u3.w};
        const float* Wj = W + (size_t)j * 640;
        float uh[40];
        #pragma unroll
        for (int co = 0; co < 40; co++) {
            const float4* wp = (const float4*)(Wj + co * 16);
            float4 w0 = wp[0], w1 = wp[1], w2 = wp[2], w3 = wp[3];
            uh[co] = w0.x * uu[0]  + w0.y * uu[1]  + w0.z * uu[2]  + w0.w * uu[3]
                   + w1.x * uu[4]  + w1.y * uu[5]  + w1.z * uu[6]  + w1.w * uu[7]
                   + w2.x * uu[8]  + w2.y * uu[9]  + w2.z * uu[10] + w2.w * uu[11]
                   + w3.x * uu[12] + w3.y * uu[13] + w3.z * uu[14] + w3.w * uu[15];
        }
        float blog[10];
        float mx = -1e30f;
        #pragma unroll
        for (int c = 0; c < 10; c++) {
            float dd = uh[c * 4 + 0] * svb[c * 4 + 0] + uh[c * 4 + 1] * svb[c * 4 + 1]
                     + uh[c * 4 + 2] * svb[c * 4 + 2] + uh[c * 4 + 3] * svb[c * 4 + 3];
            blog[c] = dd;
            mx = fmaxf(mx, dd);
        }
        float sum = 0.f;
        #pragma unroll
        for (int c = 0; c < 10; c++) {
            blog[c] = __expf(blog[c] - mx);
            sum += blog[c];
        }
        float inv = 1.f / sum;
        #pragma unroll
        for (int c = 0; c < 10; c++) {
            float cw = blog[c] * inv;
            sacc[c * 4 + 0] += cw * uh[c * 4 + 0];
            sacc[c * 4 + 1] += cw * uh[c * 4 + 1];
            sacc[c * 4 + 2] += cw * uh[c * 4 + 2];
            sacc[c * 4 + 3] += cw * uh[c * 4 + 3];
        }
    }
    #pragma unroll
    for (int i = 0; i < 40; i++) atomicAdd(&ssum[b * 40 + i], sacc[i]);
    __syncthreads();
    for (int i = tid; i < 1280; i += 256) atomicAdd(&g_s[i], ssum[i]);
}

// ---------------- v = squash(s); Vacc += v; zero s; final softmax on last ----------------
__global__ void k_vupdate(float* __restrict__ out, int last) {
    __shared__ float slen[320];
    const int tid = threadIdx.x;
    const int b = tid / 10;
    float s0 = g_s[tid * 4 + 0], s1 = g_s[tid * 4 + 1];
    float s2 = g_s[tid * 4 + 2], s3 = g_s[tid * 4 + 3];
    float n2 = s0 * s0 + s1 * s1 + s2 * s2 + s3 * s3;
    float sc = (n2 / (1.f + n2)) / sqrtf(n2 + 1e-8f);
    float v0 = s0 * sc, v1 = s1 * sc, v2 = s2 * sc, v3 = s3 * sc;
    g_vacc[tid * 4 + 0] += v0; g_vacc[tid * 4 + 1] += v1;
    g_vacc[tid * 4 + 2] += v2; g_vacc[tid * 4 + 3] += v3;
    g_s[tid * 4 + 0] = 0.f; g_s[tid * 4 + 1] = 0.f;
    g_s[tid * 4 + 2] = 0.f; g_s[tid * 4 + 3] = 0.f;
    if (last) {
        slen[tid] = sqrtf(v0 * v0 + v1 * v1 + v2 * v2 + v3 * v3);
        __syncthreads();
        float mx = -1e30f;
        for (int c = 0; c < 10; c++) mx = fmaxf(mx, slen[b * 10 + c]);
        float sum = 0.f;
        for (int c = 0; c < 10; c++) sum += expf(slen[b * 10 + c] - mx);
        out[tid] = expf(slen[tid] - mx) / sum;
    }
}

// ---------------- launch ----------------
extern "C" void kernel_launch(void* const* d_in, const int* in_sizes, int n_in,
                              void* d_out, int out_size) {
    const float* x       = (const float*)d_in[0];
    const float* conv_w  = (const float*)d_in[1];
    const float* conv_b  = (const float*)d_in[2];
    const float* pcaps_w = (const float*)d_in[3];
    const float* pcaps_b = (const float*)d_in[4];
    const float* route_W = (const float*)d_in[5];
    float* out = (float*)d_out;
    (void)in_sizes; (void)n_in; (void)out_size;

    cudaFuncSetAttribute(k_gemm_mma, cudaFuncAttributeMaxDynamicSharedMemorySize, SMEM_DYN);

    k_zero<<<1, 256>>>();
    k_conv1<<<dim3(8, 32), 256>>>(x, conv_w, conv_b);
    k_cvtW<<<2048, 256>>>(pcaps_w);
    k_im2col_cvt<<<NPAD, 256>>>();
    k_gemm_mma<<<dim3(NPAD / N_TILE, OC2 / M_TILE), 256, SMEM_DYN>>>();
    k_form_u<<<dim3(C0, B_), 192>>>(pcaps_b);
    for (int t = 0; t < 8; t++) {
        k_route<<<ROUTES / NPOS, 256>>>(route_W);
        k_vupdate<<<1, 320>>>(out, t == 7);
    }
}